// round 7
// baseline (speedup 1.0000x reference)
#include <cuda_runtime.h>
#include <math.h>

// Problem constants
#define TT   2048
#define BB   32
#define ICC  512
#define HCC  512
#define LLL  2

// Recurrence config: CTA = (batch group bg, channel group cg)
#define NCTA 128
#define RTH  256
#define NBG  8        // batch groups (4 batches each)
#define NCG  16       // channel groups (32 channels each)
#define BPG  4        // batches per CTA
#define CPG  32       // channels per CTA

// Projection GEMM config
#define PBM 128
#define PBN 128
#define PBK 16
#define PLD (PBM + 4)

// ---------------------------------------------------------------------------
// Scratch (static device globals: allocation-free per harness rules)
// ---------------------------------------------------------------------------
__device__ float g_xproj[(size_t)TT * BB * HCC];
__device__ float g_ys0[(size_t)TT * BB * HCC];
__device__ float g_h[2][BB * HCC];          // ping-pong h, layout [b][c]
__device__ unsigned g_flag[NBG][32];        // per-CTA publish counters (128B/group)
__device__ unsigned g_gc[NBG];              // exit-barrier counters (self-reset)
__device__ volatile unsigned g_ggen[NBG];   // exit-barrier generations (monotonic)

__device__ __forceinline__ unsigned ld_acq(const unsigned* p) {
    unsigned v;
    asm volatile("ld.acquire.gpu.global.u32 %0, [%1];" : "=r"(v) : "l"(p) : "memory");
    return v;
}
__device__ __forceinline__ void st_rel(unsigned* p, unsigned v) {
    asm volatile("st.release.gpu.global.u32 [%0], %1;" :: "l"(p), "r"(v) : "memory");
}

// ---------------------------------------------------------------------------
// Projection GEMM (unchanged): C[row,n] = A[row,:] . W[n,:] + bias[n]
// ---------------------------------------------------------------------------
__global__ __launch_bounds__(256, 2)
void proj_kernel(const float* __restrict__ Xin, const float* __restrict__ Wp,
                 const float* __restrict__ bp, int use_internal)
{
    const float* A = use_internal ? (const float*)g_ys0 : Xin;
    __shared__ float As[PBK][PLD];
    __shared__ float Bs[PBK][PLD];

    const int t  = threadIdx.x;
    const int m0 = blockIdx.y * PBM;
    const int n0 = blockIdx.x * PBN;
    const int lr = t >> 1;
    const int lc = (t & 1) << 3;
    const int tx = t & 15;
    const int ty = t >> 4;

    float acc[8][8];
#pragma unroll
    for (int i = 0; i < 8; i++)
#pragma unroll
        for (int j = 0; j < 8; j++) acc[i][j] = 0.f;

    const float* Ag = A  + (size_t)(m0 + lr) * ICC;
    const float* Bg = Wp + (size_t)(n0 + lr) * ICC;

    for (int k0 = 0; k0 < ICC; k0 += PBK) {
        float4 a0 = __ldg((const float4*)(Ag + k0 + lc));
        float4 a1 = __ldg((const float4*)(Ag + k0 + lc + 4));
        float4 b0 = __ldg((const float4*)(Bg + k0 + lc));
        float4 b1 = __ldg((const float4*)(Bg + k0 + lc + 4));
        As[lc+0][lr] = a0.x; As[lc+1][lr] = a0.y; As[lc+2][lr] = a0.z; As[lc+3][lr] = a0.w;
        As[lc+4][lr] = a1.x; As[lc+5][lr] = a1.y; As[lc+6][lr] = a1.z; As[lc+7][lr] = a1.w;
        Bs[lc+0][lr] = b0.x; Bs[lc+1][lr] = b0.y; Bs[lc+2][lr] = b0.z; Bs[lc+3][lr] = b0.w;
        Bs[lc+4][lr] = b1.x; Bs[lc+5][lr] = b1.y; Bs[lc+6][lr] = b1.z; Bs[lc+7][lr] = b1.w;
        __syncthreads();
#pragma unroll
        for (int k = 0; k < PBK; k++) {
            float4 am0 = *(const float4*)&As[k][ty * 8];
            float4 am1 = *(const float4*)&As[k][ty * 8 + 4];
            float4 bn0 = *(const float4*)&Bs[k][tx * 8];
            float4 bn1 = *(const float4*)&Bs[k][tx * 8 + 4];
            float am[8] = {am0.x, am0.y, am0.z, am0.w, am1.x, am1.y, am1.z, am1.w};
            float bn[8] = {bn0.x, bn0.y, bn0.z, bn0.w, bn1.x, bn1.y, bn1.z, bn1.w};
#pragma unroll
            for (int i = 0; i < 8; i++)
#pragma unroll
                for (int j = 0; j < 8; j++)
                    acc[i][j] = fmaf(am[i], bn[j], acc[i][j]);
        }
        __syncthreads();
    }

    float4 bv0 = __ldg((const float4*)(bp + n0 + tx * 8));
    float4 bv1 = __ldg((const float4*)(bp + n0 + tx * 8 + 4));
#pragma unroll
    for (int i = 0; i < 8; i++) {
        size_t row = (size_t)(m0 + ty * 8 + i);
        float4 o0 = make_float4(acc[i][0] + bv0.x, acc[i][1] + bv0.y,
                                acc[i][2] + bv0.z, acc[i][3] + bv0.w);
        float4 o1 = make_float4(acc[i][4] + bv1.x, acc[i][5] + bv1.y,
                                acc[i][6] + bv1.z, acc[i][7] + bv1.w);
        *(float4*)&g_xproj[row * HCC + n0 + tx * 8]     = o0;
        *(float4*)&g_xproj[row * HCC + n0 + tx * 8 + 4] = o1;
    }
}

// ---------------------------------------------------------------------------
// Recurrence. CTA(bg,cg): batches [4bg,4bg+4), channels [32cg,32cg+32).
// Thread (warp=ks in 8, lane=c in 32): Wh[c0+lane][64ks..+64] lives in 64
// REGISTERS for all 2048 steps. h read warp-uniform from L2 (__ldcg float4,
// 1 request/warp, broadcast). 8-way k partials reduced via smem; 128 threads
// do tanh + stores. Sync = per-CTA release flags; each CTA waits only on the
// 16 flags of its batch group (8 independent groups, no chip-wide barrier).
// ---------------------------------------------------------------------------
__global__ __launch_bounds__(RTH, 1)
void rec_kernel(const float* __restrict__ Wh, const float* __restrict__ bh,
                float* __restrict__ out_ys, float* __restrict__ out_hs,
                int write_internal)
{
    __shared__ float red[8 * 128];   // [ks][b*32+c] partials

    const int t    = threadIdx.x;
    const int bid  = blockIdx.x;
    const int bg   = bid >> 4;
    const int cg   = bid & 15;
    const int b0   = bg * BPG;
    const int c0   = cg * CPG;
    const int wid  = t >> 5;         // k-slice
    const int lane = t & 31;         // channel within group

    float* ysp = write_internal ? (float*)g_ys0 : out_ys;

    // Step-invariant weights -> registers (64 floats/thread).
    float4 wr[16];
    const float* wrow = Wh + (size_t)(c0 + lane) * HCC + wid * 64;
#pragma unroll
    for (int j = 0; j < 16; j++) wr[j] = __ldg((const float4*)(wrow + 4 * j));

    // Zero my slice of h[0]; load bias for epilogue.
    float bhv = 0.f;
    if (t < 128) {
        int b = t >> 5, c = t & 31;
        g_h[0][(b0 + b) * HCC + c0 + c] = 0.f;
        bhv = __ldg(bh + c0 + c);
    }
    __syncthreads();
    if (t == 0) st_rel(&g_flag[bg][cg], 1u);   // publish #1 (h0 ready)

    const unsigned* myf = &g_flag[bg][lane & 15];

    for (int s = 0; s < TT; s++) {
        // Prefetch xproj (independent of sync).
        float xpv = 0.f;
        if (t < 128)
            xpv = __ldg(&g_xproj[(size_t)s * (BB * HCC) +
                                 (size_t)(b0 + (t >> 5)) * HCC + c0 + (t & 31)]);

        // Wait for all 16 producers of this batch group (flags >= s+1).
        const unsigned need = (unsigned)(s + 1);
        for (;;) {
            unsigned v = ld_acq(myf);
            if (__all_sync(0xffffffffu, v >= need)) break;
        }

        const float* hb = g_h[s & 1] + b0 * HCC + wid * 64;
        float a0 = 0.f, a1 = 0.f, a2 = 0.f, a3 = 0.f;
#pragma unroll
        for (int j = 0; j < 16; j++) {
            float4 w  = wr[j];
            float4 h0 = __ldcg((const float4*)(hb + 0 * HCC + 4 * j));
            float4 h1 = __ldcg((const float4*)(hb + 1 * HCC + 4 * j));
            float4 h2 = __ldcg((const float4*)(hb + 2 * HCC + 4 * j));
            float4 h3 = __ldcg((const float4*)(hb + 3 * HCC + 4 * j));
            a0 = fmaf(w.x, h0.x, a0); a0 = fmaf(w.y, h0.y, a0);
            a0 = fmaf(w.z, h0.z, a0); a0 = fmaf(w.w, h0.w, a0);
            a1 = fmaf(w.x, h1.x, a1); a1 = fmaf(w.y, h1.y, a1);
            a1 = fmaf(w.z, h1.z, a1); a1 = fmaf(w.w, h1.w, a1);
            a2 = fmaf(w.x, h2.x, a2); a2 = fmaf(w.y, h2.y, a2);
            a2 = fmaf(w.z, h2.z, a2); a2 = fmaf(w.w, h2.w, a2);
            a3 = fmaf(w.x, h3.x, a3); a3 = fmaf(w.y, h3.y, a3);
            a3 = fmaf(w.z, h3.z, a3); a3 = fmaf(w.w, h3.w, a3);
        }
        red[wid * 128 + 0 * 32 + lane] = a0;
        red[wid * 128 + 1 * 32 + lane] = a1;
        red[wid * 128 + 2 * 32 + lane] = a2;
        red[wid * 128 + 3 * 32 + lane] = a3;
        __syncthreads();

        if (t < 128) {
            float sum = xpv + bhv;
#pragma unroll
            for (int k = 0; k < 8; k++) sum += red[k * 128 + t];
            float hn = tanhf(sum);
            int b = t >> 5, c = t & 31;
            size_t oi = (size_t)(b0 + b) * HCC + c0 + c;
            ysp[(size_t)s * (BB * HCC) + oi] = hn;
            g_h[(s + 1) & 1][oi] = hn;
            if (s == TT - 1) out_hs[oi] = hn;
        }
        __syncthreads();
        if (t == 0) st_rel(&g_flag[bg][cg], (unsigned)(s + 2));
    }

    // Reset flags for the next launch / graph replay. Group barrier first so
    // no peer is still spinning on our flag; counters self-reset, generations
    // are monotonic (equality-compared only) -> replay-safe.
    if (t == 0) {
        unsigned g = g_ggen[bg];
        __threadfence();
        if (atomicAdd(&g_gc[bg], 1u) == NCG - 1) {
            g_gc[bg] = 0u;
            __threadfence();
            g_ggen[bg] = g + 1u;
        } else {
            while (g_ggen[bg] == g) { }
        }
        g_flag[bg][cg] = 0u;   // visible to next launch via stream ordering
    }
}

// ---------------------------------------------------------------------------
// Output layout: [hs (L,B,HC) | inp (T,B,HC)]
// ---------------------------------------------------------------------------
extern "C" void kernel_launch(void* const* d_in, const int* in_sizes, int n_in,
                              void* d_out, int out_size) {
    const float* x  = (const float*)d_in[0];
    const float* Wi = (const float*)d_in[1];
    const float* bi = (const float*)d_in[2];
    const float* Wh = (const float*)d_in[3];
    const float* bh = (const float*)d_in[4];
    float* out = (float*)d_out;

    dim3 pg(HCC / PBN, (TT * BB) / PBM);  // (4, 512)

    // Layer 0
    proj_kernel<<<pg, 256>>>(x, Wi, bi, 0);
    rec_kernel<<<NCTA, RTH>>>(Wh, bh, nullptr, out, 1);

    // Layer 1
    proj_kernel<<<pg, 256>>>(x, Wi + HCC * ICC, bi + HCC, 1);
    rec_kernel<<<NCTA, RTH>>>(Wh + HCC * HCC, bh + HCC,
                              out + (size_t)LLL * BB * HCC,  // inp region
                              out + BB * HCC,                // hs[1]
                              0);
}

// round 8
// speedup vs baseline: 1.8011x; 1.8011x over previous
#include <cuda_runtime.h>
#include <math.h>

// Problem constants
#define TT   2048
#define BB   32
#define ICC  512
#define HCC  512
#define LLL  2

// Recurrence config: CTA = (batch group bg, channel group cg)
#define NCTA 128
#define RTH  256
#define NBG  8        // batch groups (4 batches each), independent sync domains
#define NCG  16       // channel groups (32 channels each) per batch group
#define BPG  4
#define CPG  32

// Dynamic smem partition for rec kernel (floats)
#define W_ELEMS   (CPG * HCC)        // 16384 (64 KB) swizzled weight slice
#define H_ELEMS   (BPG * HCC)        // 2048  (8 KB) staged h
#define RED_ELEMS (8 * 128)          // 1024  (4 KB) k-split partials
#define REC_SMEM_BYTES ((W_ELEMS + H_ELEMS + RED_ELEMS) * 4)

// Projection GEMM config
#define PBM 128
#define PBN 128
#define PBK 16
#define PLD (PBM + 4)

// ---------------------------------------------------------------------------
// Scratch (static device globals: allocation-free per harness rules)
// ---------------------------------------------------------------------------
__device__ float g_xproj[(size_t)TT * BB * HCC];
__device__ float g_ys0[(size_t)TT * BB * HCC];
__device__ float g_h[2][BB * HCC];               // ping-pong h, layout [b][c]
__device__ unsigned g_bcnt[NBG * 32];            // per-group arrive counters (128B apart)
__device__ volatile unsigned g_bgen[NBG * 32];   // per-group generations (monotonic)

// ---------------------------------------------------------------------------
// Per-batch-group barrier: R3's proven sense-reversing central-atomic design,
// scoped to the 16 CTAs of one batch group. Counter self-resets each use;
// generation is monotonic and only equality-compared -> graph-replay safe.
// All 16 CTAs of a group are co-resident (128 CTAs <= 148 SMs, 1 CTA/SM).
// ---------------------------------------------------------------------------
__device__ __forceinline__ void group_bar(int bg) {
    __syncthreads();
    if (threadIdx.x == 0) {
        const int gi = bg * 32;
        unsigned g = g_bgen[gi];
        __threadfence();  // release this CTA's h writes
        if (atomicAdd(&g_bcnt[gi], 1u) == NCG - 1) {
            g_bcnt[gi] = 0u;
            __threadfence();
            g_bgen[gi] = g + 1u;
        } else {
            while (g_bgen[gi] == g) { }
        }
        __threadfence();  // acquire peers' h writes
    }
    __syncthreads();
}

// ---------------------------------------------------------------------------
// Projection GEMM (unchanged, proven): C[row,n] = A[row,:] . W[n,:] + b[n]
// ---------------------------------------------------------------------------
__global__ __launch_bounds__(256, 2)
void proj_kernel(const float* __restrict__ Xin, const float* __restrict__ Wp,
                 const float* __restrict__ bp, int use_internal)
{
    const float* A = use_internal ? (const float*)g_ys0 : Xin;
    __shared__ float As[PBK][PLD];
    __shared__ float Bs[PBK][PLD];

    const int t  = threadIdx.x;
    const int m0 = blockIdx.y * PBM;
    const int n0 = blockIdx.x * PBN;
    const int lr = t >> 1;
    const int lc = (t & 1) << 3;
    const int tx = t & 15;
    const int ty = t >> 4;

    float acc[8][8];
#pragma unroll
    for (int i = 0; i < 8; i++)
#pragma unroll
        for (int j = 0; j < 8; j++) acc[i][j] = 0.f;

    const float* Ag = A  + (size_t)(m0 + lr) * ICC;
    const float* Bg = Wp + (size_t)(n0 + lr) * ICC;

    for (int k0 = 0; k0 < ICC; k0 += PBK) {
        float4 a0 = __ldg((const float4*)(Ag + k0 + lc));
        float4 a1 = __ldg((const float4*)(Ag + k0 + lc + 4));
        float4 b0 = __ldg((const float4*)(Bg + k0 + lc));
        float4 b1 = __ldg((const float4*)(Bg + k0 + lc + 4));
        As[lc+0][lr] = a0.x; As[lc+1][lr] = a0.y; As[lc+2][lr] = a0.z; As[lc+3][lr] = a0.w;
        As[lc+4][lr] = a1.x; As[lc+5][lr] = a1.y; As[lc+6][lr] = a1.z; As[lc+7][lr] = a1.w;
        Bs[lc+0][lr] = b0.x; Bs[lc+1][lr] = b0.y; Bs[lc+2][lr] = b0.z; Bs[lc+3][lr] = b0.w;
        Bs[lc+4][lr] = b1.x; Bs[lc+5][lr] = b1.y; Bs[lc+6][lr] = b1.z; Bs[lc+7][lr] = b1.w;
        __syncthreads();
#pragma unroll
        for (int k = 0; k < PBK; k++) {
            float4 am0 = *(const float4*)&As[k][ty * 8];
            float4 am1 = *(const float4*)&As[k][ty * 8 + 4];
            float4 bn0 = *(const float4*)&Bs[k][tx * 8];
            float4 bn1 = *(const float4*)&Bs[k][tx * 8 + 4];
            float am[8] = {am0.x, am0.y, am0.z, am0.w, am1.x, am1.y, am1.z, am1.w};
            float bn[8] = {bn0.x, bn0.y, bn0.z, bn0.w, bn1.x, bn1.y, bn1.z, bn1.w};
#pragma unroll
            for (int i = 0; i < 8; i++)
#pragma unroll
                for (int j = 0; j < 8; j++)
                    acc[i][j] = fmaf(am[i], bn[j], acc[i][j]);
        }
        __syncthreads();
    }

    float4 bv0 = __ldg((const float4*)(bp + n0 + tx * 8));
    float4 bv1 = __ldg((const float4*)(bp + n0 + tx * 8 + 4));
#pragma unroll
    for (int i = 0; i < 8; i++) {
        size_t row = (size_t)(m0 + ty * 8 + i);
        float4 o0 = make_float4(acc[i][0] + bv0.x, acc[i][1] + bv0.y,
                                acc[i][2] + bv0.z, acc[i][3] + bv0.w);
        float4 o1 = make_float4(acc[i][4] + bv1.x, acc[i][5] + bv1.y,
                                acc[i][6] + bv1.z, acc[i][7] + bv1.w);
        *(float4*)&g_xproj[row * HCC + n0 + tx * 8]     = o0;
        *(float4*)&g_xproj[row * HCC + n0 + tx * 8 + 4] = o1;
    }
}

// ---------------------------------------------------------------------------
// Recurrence. CTA(bg,cg): batches [4bg,4bg+4), channels [32cg,32cg+32).
// Wh slice (32x512) lives in XOR-swizzled smem (conflict-free LDS.128 when
// each lane reads a different channel row). h (4x512 = 8KB) is staged into
// smem each step with coalesced LDGs, then consumed via broadcast LDS.
// Thread (warp=ks in 8, lane=c in 32): partial dot over 64-wide k-slice for
// channel c, all 4 batches (256 FMA). 8-way k reduction via smem; 128
// threads do tanh + stores. Sync = per-batch-group sense-reversing barrier.
// ---------------------------------------------------------------------------
__global__ __launch_bounds__(RTH, 1)
void rec_kernel(const float* __restrict__ Wh, const float* __restrict__ bh,
                float* __restrict__ out_ys, float* __restrict__ out_hs,
                int write_internal)
{
    extern __shared__ float smem[];
    float* w_s = smem;                       // [32][512] swizzled (f4 granularity)
    float* h_s = smem + W_ELEMS;             // [4][512]
    float* red = smem + W_ELEMS + H_ELEMS;   // [8][128]

    const int t    = threadIdx.x;
    const int bid  = blockIdx.x;
    const int bg   = bid >> 4;
    const int cg   = bid & 15;
    const int b0   = bg * BPG;
    const int c0   = cg * CPG;
    const int ks   = t >> 5;                 // k-slice (64 wide)
    const int lane = t & 31;                 // channel within group

    float* ysp = write_internal ? (float*)g_ys0 : out_ys;

    // Load Wh slice into swizzled smem.
    // f4 element (row c, kf4) stored at f4-index c*128 + (kf4 ^ (c & 7)).
    {
        float4* wd = (float4*)w_s;
        const float4* wsrc = (const float4*)(Wh + (size_t)c0 * HCC);
#pragma unroll
        for (int idx = t; idx < CPG * (HCC / 4); idx += RTH) {
            int row = idx >> 7;           // channel row 0..31
            int kf4 = idx & 127;          // float4 index within row
            wd[row * 128 + (kf4 ^ (row & 7))] = __ldg(wsrc + idx);
        }
    }

    // Zero this CTA's slice of h[0]; load bias for epilogue.
    float bhv = 0.f;
    if (t < 128) {
        int b = t >> 5, c = t & 31;
        g_h[0][(b0 + b) * HCC + c0 + c] = 0.f;
        bhv = __ldg(bh + c0 + c);
    }
    group_bar(bg);   // h[0] visible + w_s ready (includes __syncthreads)

    for (int s = 0; s < TT; s++) {
        // Prefetch xproj (depends only on s; independent of the h chain).
        float xpv = 0.f;
        if (t < 128)
            xpv = __ldg(&g_xproj[(size_t)s * (BB * HCC) +
                                 (size_t)(b0 + (t >> 5)) * HCC + c0 + (t & 31)]);

        // Stage h[cur] for this batch group: 2048 contiguous floats, coalesced.
        {
            const float4* hsrc = (const float4*)(g_h[s & 1] + b0 * HCC);
            float4* hdst = (float4*)h_s;
            hdst[t]       = hsrc[t];
            hdst[t + 256] = hsrc[t + 256];
        }
        __syncthreads();

        const int kbase = ks * 16;   // f4 index base of this warp's k-slice
        const float* hb = h_s + kbase * 4;
        float a0 = 0.f, a1 = 0.f, a2 = 0.f, a3 = 0.f;
#pragma unroll
        for (int j = 0; j < 16; j++) {
            float4 w  = ((const float4*)w_s)[lane * 128 + ((kbase + j) ^ (lane & 7))];
            float4 h0 = *(const float4*)(hb + 0 * HCC + 4 * j);
            float4 h1 = *(const float4*)(hb + 1 * HCC + 4 * j);
            float4 h2 = *(const float4*)(hb + 2 * HCC + 4 * j);
            float4 h3 = *(const float4*)(hb + 3 * HCC + 4 * j);
            a0 = fmaf(w.x, h0.x, a0); a0 = fmaf(w.y, h0.y, a0);
            a0 = fmaf(w.z, h0.z, a0); a0 = fmaf(w.w, h0.w, a0);
            a1 = fmaf(w.x, h1.x, a1); a1 = fmaf(w.y, h1.y, a1);
            a1 = fmaf(w.z, h1.z, a1); a1 = fmaf(w.w, h1.w, a1);
            a2 = fmaf(w.x, h2.x, a2); a2 = fmaf(w.y, h2.y, a2);
            a2 = fmaf(w.z, h2.z, a2); a2 = fmaf(w.w, h2.w, a2);
            a3 = fmaf(w.x, h3.x, a3); a3 = fmaf(w.y, h3.y, a3);
            a3 = fmaf(w.z, h3.z, a3); a3 = fmaf(w.w, h3.w, a3);
        }
        red[ks * 128 + 0 * 32 + lane] = a0;
        red[ks * 128 + 1 * 32 + lane] = a1;
        red[ks * 128 + 2 * 32 + lane] = a2;
        red[ks * 128 + 3 * 32 + lane] = a3;
        __syncthreads();

        if (t < 128) {
            float sum = xpv + bhv;
#pragma unroll
            for (int k = 0; k < 8; k++) sum += red[k * 128 + t];
            float hn = tanhf(sum);
            int b = t >> 5, c = t & 31;
            size_t oi = (size_t)(b0 + b) * HCC + c0 + c;
            ysp[(size_t)s * (BB * HCC) + oi] = hn;
            g_h[(s + 1) & 1][oi] = hn;
            if (s == TT - 1) out_hs[oi] = hn;
        }
        group_bar(bg);   // publish h_new within the batch group
    }
}

// ---------------------------------------------------------------------------
// Output layout: [hs (L,B,HC) | inp (T,B,HC)]
// ---------------------------------------------------------------------------
extern "C" void kernel_launch(void* const* d_in, const int* in_sizes, int n_in,
                              void* d_out, int out_size) {
    const float* x  = (const float*)d_in[0];
    const float* Wi = (const float*)d_in[1];
    const float* bi = (const float*)d_in[2];
    const float* Wh = (const float*)d_in[3];
    const float* bh = (const float*)d_in[4];
    float* out = (float*)d_out;

    // Opt in to >48KB dynamic smem (host attribute set, not an allocation;
    // idempotent and capture-safe).
    cudaFuncSetAttribute(rec_kernel, cudaFuncAttributeMaxDynamicSharedMemorySize,
                         REC_SMEM_BYTES);

    dim3 pg(HCC / PBN, (TT * BB) / PBM);  // (4, 512)

    // Layer 0
    proj_kernel<<<pg, 256>>>(x, Wi, bi, 0);
    rec_kernel<<<NCTA, RTH, REC_SMEM_BYTES>>>(Wh, bh, nullptr, out, 1);

    // Layer 1
    proj_kernel<<<pg, 256>>>(x, Wi + HCC * ICC, bi + HCC, 1);
    rec_kernel<<<NCTA, RTH, REC_SMEM_BYTES>>>(Wh + HCC * HCC, bh + HCC,
                                              out + (size_t)LLL * BB * HCC,
                                              out + BB * HCC,
                                              0);
}

// round 10
// speedup vs baseline: 2.0760x; 1.1527x over previous
#include <cuda_runtime.h>
#include <math.h>
#include <stdint.h>

// Problem constants
#define TT   2048
#define BB   32
#define ICC  512
#define HCC  512
#define LLL  2

// Recurrence: 16 clusters... actually 16 batch groups x 8 channel groups.
// Cluster = 8 CTAs = one batch group (2 batches), each CTA owns 64 channels.
#define CSIZE 8
#define NCTA  128
#define RTH   256
#define BPG   2      // batches per CTA
#define CPG   64     // channels per CTA

// Projection GEMM config
#define PBM 128
#define PBN 128
#define PBK 16
#define PLD (PBM + 4)

// ---------------------------------------------------------------------------
// Scratch (static device globals: allocation-free per harness rules)
// ---------------------------------------------------------------------------
__device__ float g_xproj[(size_t)TT * BB * HCC];
__device__ float g_ys0[(size_t)TT * BB * HCC];

// ---------------------------------------------------------------------------
// Cluster helpers
// ---------------------------------------------------------------------------
__device__ __forceinline__ uint32_t smem_u32(const void* p) {
    uint32_t a;
    asm("{ .reg .u64 t; cvta.to.shared.u64 t, %1; cvt.u32.u64 %0, t; }"
        : "=r"(a) : "l"(p));
    return a;
}
__device__ __forceinline__ uint32_t mapa_u32(uint32_t a, uint32_t rank) {
    uint32_t r;
    asm("mapa.shared::cluster.u32 %0, %1, %2;" : "=r"(r) : "r"(a), "r"(rank));
    return r;
}
__device__ __forceinline__ float4 ld_cluster_f4(uint32_t a) {
    float4 v;
    asm volatile("ld.shared::cluster.v4.f32 {%0,%1,%2,%3}, [%4];"
                 : "=f"(v.x), "=f"(v.y), "=f"(v.z), "=f"(v.w) : "r"(a) : "memory");
    return v;
}
#define CL_ARRIVE() asm volatile("barrier.cluster.arrive.aligned;" ::: "memory")
#define CL_WAIT()   asm volatile("barrier.cluster.wait.aligned;"   ::: "memory")

// ---------------------------------------------------------------------------
// Projection GEMM (unchanged, proven): C[row,n] = A[row,:] . W[n,:] + b[n]
// ---------------------------------------------------------------------------
__global__ __launch_bounds__(256, 2)
void proj_kernel(const float* __restrict__ Xin, const float* __restrict__ Wp,
                 const float* __restrict__ bp, int use_internal)
{
    const float* A = use_internal ? (const float*)g_ys0 : Xin;
    __shared__ float As[PBK][PLD];
    __shared__ float Bs[PBK][PLD];

    const int t  = threadIdx.x;
    const int m0 = blockIdx.y * PBM;
    const int n0 = blockIdx.x * PBN;
    const int lr = t >> 1;
    const int lc = (t & 1) << 3;
    const int tx = t & 15;
    const int ty = t >> 4;

    float acc[8][8];
#pragma unroll
    for (int i = 0; i < 8; i++)
#pragma unroll
        for (int j = 0; j < 8; j++) acc[i][j] = 0.f;

    const float* Ag = A  + (size_t)(m0 + lr) * ICC;
    const float* Bg = Wp + (size_t)(n0 + lr) * ICC;

    for (int k0 = 0; k0 < ICC; k0 += PBK) {
        float4 a0 = __ldg((const float4*)(Ag + k0 + lc));
        float4 a1 = __ldg((const float4*)(Ag + k0 + lc + 4));
        float4 b0 = __ldg((const float4*)(Bg + k0 + lc));
        float4 b1 = __ldg((const float4*)(Bg + k0 + lc + 4));
        As[lc+0][lr] = a0.x; As[lc+1][lr] = a0.y; As[lc+2][lr] = a0.z; As[lc+3][lr] = a0.w;
        As[lc+4][lr] = a1.x; As[lc+5][lr] = a1.y; As[lc+6][lr] = a1.z; As[lc+7][lr] = a1.w;
        Bs[lc+0][lr] = b0.x; Bs[lc+1][lr] = b0.y; Bs[lc+2][lr] = b0.z; Bs[lc+3][lr] = b0.w;
        Bs[lc+4][lr] = b1.x; Bs[lc+5][lr] = b1.y; Bs[lc+6][lr] = b1.z; Bs[lc+7][lr] = b1.w;
        __syncthreads();
#pragma unroll
        for (int k = 0; k < PBK; k++) {
            float4 am0 = *(const float4*)&As[k][ty * 8];
            float4 am1 = *(const float4*)&As[k][ty * 8 + 4];
            float4 bn0 = *(const float4*)&Bs[k][tx * 8];
            float4 bn1 = *(const float4*)&Bs[k][tx * 8 + 4];
            float am[8] = {am0.x, am0.y, am0.z, am0.w, am1.x, am1.y, am1.z, am1.w};
            float bn[8] = {bn0.x, bn0.y, bn0.z, bn0.w, bn1.x, bn1.y, bn1.z, bn1.w};
#pragma unroll
            for (int i = 0; i < 8; i++)
#pragma unroll
                for (int j = 0; j < 8; j++)
                    acc[i][j] = fmaf(am[i], bn[j], acc[i][j]);
        }
        __syncthreads();
    }

    float4 bv0 = __ldg((const float4*)(bp + n0 + tx * 8));
    float4 bv1 = __ldg((const float4*)(bp + n0 + tx * 8 + 4));
#pragma unroll
    for (int i = 0; i < 8; i++) {
        size_t row = (size_t)(m0 + ty * 8 + i);
        float4 o0 = make_float4(acc[i][0] + bv0.x, acc[i][1] + bv0.y,
                                acc[i][2] + bv0.z, acc[i][3] + bv0.w);
        float4 o1 = make_float4(acc[i][4] + bv1.x, acc[i][5] + bv1.y,
                                acc[i][6] + bv1.z, acc[i][7] + bv1.w);
        *(float4*)&g_xproj[row * HCC + n0 + tx * 8]     = o0;
        *(float4*)&g_xproj[row * HCC + n0 + tx * 8 + 4] = o1;
    }
}

// ---------------------------------------------------------------------------
// Recurrence, cluster edition. Cluster rank = cg (0..7). CTA(bg,cg):
// batches {2bg, 2bg+1}, channels [64cg, 64cg+64).
//  - Wh slice in REGISTERS: thread (warp w, lane): channel c=(w&1)*32+lane,
//    k-slice ks=w>>1 covering 128 k -> 32 float4 (step-invariant).
//  - h lives ONLY in smem: each CTA publishes its 128-float slice in hpub
//    (double-buffered); each thread pulls one float4 from peer (rank = warp
//    id) via mapa + ld.shared::cluster into the staging buffer hs4.
//  - Sync: split HW cluster barrier; arrive right after the epilogue's smem
//    publish (release), wait at loop top (acquire). xproj LDG prefetch sits
//    between arrive and wait to hide its latency.
// ---------------------------------------------------------------------------
__global__ __launch_bounds__(RTH, 1) __cluster_dims__(CSIZE, 1, 1)
void rec_kernel(const float* __restrict__ Wh, const float* __restrict__ bh,
                float* __restrict__ out_ys, float* __restrict__ out_hs,
                int write_internal)
{
    __shared__ float4 hs4[BPG * 128];          // staged full h for 2 batches (4 KB)
    __shared__ float  hpub[2][BPG * CPG];      // published own slice, double buffer
    __shared__ float  red[4 * 128];            // k-split partials

    const int t    = threadIdx.x;
    const int bid  = blockIdx.x;
    const int bg   = bid >> 3;
    const int cg   = bid & 7;
    const int b0   = bg * BPG;
    const int c0   = cg * CPG;
    const int w    = t >> 5;
    const int lane = t & 31;
    const int ks   = w >> 1;                   // k-slice 0..3 (128 k each)
    const int c    = ((w & 1) << 5) + lane;    // channel-in-group 0..63

    float* ysp = write_internal ? (float*)g_ys0 : out_ys;

    // Step-invariant weights -> registers (32 float4).
    float4 wr[32];
    {
        const float4* wsrc = (const float4*)(Wh + (size_t)(c0 + c) * HCC + ks * 128);
#pragma unroll
        for (int j = 0; j < 32; j++) wr[j] = __ldg(wsrc + j);
    }

    // Init: zero own h slice (buffer 0), load bias.
    float bhv = 0.f;
    if (t < 128) {
        hpub[0][t] = 0.f;
        bhv = __ldg(bh + c0 + (t & 63));
    }
    __syncthreads();

    // Pre-resolve remote addresses: peer w's hpub[buf] float4 #lane.
    const uint32_t loc0 = smem_u32(&hpub[0][0]) + (uint32_t)lane * 16u;
    const uint32_t loc1 = smem_u32(&hpub[1][0]) + (uint32_t)lane * 16u;
    const uint32_t rem0 = mapa_u32(loc0, (uint32_t)w);
    const uint32_t rem1 = mapa_u32(loc1, (uint32_t)w);
    // Staging dest: peer w holds channels [64w,64w+64); float4 lane encodes
    // b = lane>>4, c4 = lane&15  ->  hs4 index b*128 + w*16 + c4.
    const int dsti = ((lane >> 4) << 7) + (w << 4) + (lane & 15);

    CL_ARRIVE();   // phase 0: h0 published

    for (int s = 0; s < TT; s++) {
        // Prefetch xproj for this step (independent of the h chain).
        float xpv = 0.f;
        if (t < 128)
            xpv = __ldg(&g_xproj[(size_t)s * (BB * HCC) +
                                 (size_t)(b0 + (t >> 6)) * HCC + c0 + (t & 63)]);

        CL_WAIT();   // all peers published h[s&1]

        // Stage: one remote float4 per thread (512 B per peer slice).
        hs4[dsti] = ld_cluster_f4((s & 1) ? rem1 : rem0);
        __syncthreads();

        // Dot: c fixed, k in [128ks, 128ks+128), both batches.
        const float4* hb0 = hs4 + (ks << 5);
        const float4* hb1 = hs4 + 128 + (ks << 5);
        float a0 = 0.f, a1 = 0.f;
#pragma unroll
        for (int j = 0; j < 32; j++) {
            float4 wv = wr[j];
            float4 h0 = hb0[j];
            float4 h1 = hb1[j];
            a0 = fmaf(wv.x, h0.x, a0); a0 = fmaf(wv.y, h0.y, a0);
            a0 = fmaf(wv.z, h0.z, a0); a0 = fmaf(wv.w, h0.w, a0);
            a1 = fmaf(wv.x, h1.x, a1); a1 = fmaf(wv.y, h1.y, a1);
            a1 = fmaf(wv.z, h1.z, a1); a1 = fmaf(wv.w, h1.w, a1);
        }
        red[(ks << 7) + c]      = a0;
        red[(ks << 7) + 64 + c] = a1;
        __syncthreads();

        // Epilogue: 128 threads, output (b = t>>6, c = t&63).
        if (t < 128) {
            float sum = xpv + bhv;
#pragma unroll
            for (int k = 0; k < 4; k++) sum += red[(k << 7) + t];
            float hn = tanhf(sum);
            size_t oi = (size_t)(b0 + (t >> 6)) * HCC + c0 + (t & 63);
            ysp[(size_t)s * (BB * HCC) + oi] = hn;
            hpub[(s + 1) & 1][t] = hn;       // publish for next step
            if (s == TT - 1) out_hs[oi] = hn;
        }
        CL_ARRIVE();   // release the publish to the cluster
    }

    CL_WAIT();   // balance final arrive; no CTA exits while peers may read us
}

// ---------------------------------------------------------------------------
// Output layout: [hs (L,B,HC) | inp (T,B,HC)]
// ---------------------------------------------------------------------------
extern "C" void kernel_launch(void* const* d_in, const int* in_sizes, int n_in,
                              void* d_out, int out_size) {
    const float* x  = (const float*)d_in[0];
    const float* Wi = (const float*)d_in[1];
    const float* bi = (const float*)d_in[2];
    const float* Wh = (const float*)d_in[3];
    const float* bh = (const float*)d_in[4];
    float* out = (float*)d_out;

    dim3 pg(HCC / PBN, (TT * BB) / PBM);  // (4, 512)

    // Layer 0
    proj_kernel<<<pg, 256>>>(x, Wi, bi, 0);
    rec_kernel<<<NCTA, RTH>>>(Wh, bh, nullptr, out, 1);

    // Layer 1
    proj_kernel<<<pg, 256>>>(x, Wi + HCC * ICC, bi + HCC, 1);
    rec_kernel<<<NCTA, RTH>>>(Wh + HCC * HCC, bh + HCC,
                              out + (size_t)LLL * BB * HCC,  // inp region
                              out + BB * HCC,                // hs[1]
                              0);
}